// round 13
// baseline (speedup 1.0000x reference)
#include <cuda_runtime.h>
#include <cuda_fp16.h>
#include <cstdint>

// Problem constants
#define N_TOK 2048
#define D_IN  2048
#define D_OUT 2048
#define NE    8
#define NK    4096

// Tiling
#define BM 128
#define BN 128
#define KT 32
#define NT (D_IN / KT)
#define MAX_TILES 40

// Interleaved grid: 640 groups of 27 (26 conv blocks + 1 gemm CTA)
#define GRP 27
#define NGEMM 640
#define NCONV_ROWS 16384     // NE * D_OUT rows of W, one conv block each
#define NPANEL 128           // 16384 / 128 rows per panel

// smem (gemm role): s_flat[128] @0, 4 stages of (A fp16 + B fp16) @1024
#define SM_FLAT   0
#define SM_TILES  1024
#define TILE_B    8192
#define T_AH 0
#define T_BH TILE_B
#define STAGE_B (2*TILE_B)                      // 16 KB
#define SMEM_TOTAL (SM_TILES + 4*STAGE_B)       // 66560 -> 2 CTA/SM

// Device scratch
__device__ __half g_xh[(size_t)N_TOK * D_IN];          // 8 MB
__device__ __half g_wh[(size_t)NE * D_OUT * D_IN];     // 64 MB
__device__ float  g_y[(size_t)NK * D_OUT];             // 32 MB
__device__ int    g_cnt[NPANEL];                       // panel completion counters

__device__ __forceinline__ uint32_t SW(uint32_t off) {
    return off ^ (((off >> 7) & 3u) << 4);
}

__device__ __forceinline__ uint32_t smem_u32(const void* p) {
    uint32_t a;
    asm("{ .reg .u64 t; cvta.to.shared.u64 t, %1; cvt.u32.u64 %0, t; }" : "=r"(a) : "l"(p));
    return a;
}

__device__ __forceinline__ void cp16(uint32_t dst, const void* src) {
    asm volatile("cp.async.cg.shared.global [%0], [%1], 16;" :: "r"(dst), "l"(src) : "memory");
}
__device__ __forceinline__ void cp_commit() {
    asm volatile("cp.async.commit_group;" ::: "memory");
}
__device__ __forceinline__ void cp_wait2() {
    asm volatile("cp.async.wait_group 2;" ::: "memory");
}

__device__ __forceinline__ void ldm_x4(uint32_t& r0, uint32_t& r1, uint32_t& r2,
                                       uint32_t& r3, uint32_t addr) {
    asm volatile("ldmatrix.sync.aligned.m8n8.x4.shared.b16 {%0,%1,%2,%3}, [%4];"
                 : "=r"(r0), "=r"(r1), "=r"(r2), "=r"(r3) : "r"(addr));
}

__device__ __forceinline__ void mma_fp16(float* c, const uint32_t* a, const uint32_t* b) {
    asm volatile(
        "mma.sync.aligned.m16n8k16.row.col.f32.f16.f16.f32 "
        "{%0,%1,%2,%3}, {%4,%5,%6,%7}, {%8,%9}, {%0,%1,%2,%3};"
        : "+f"(c[0]), "+f"(c[1]), "+f"(c[2]), "+f"(c[3])
        : "r"(a[0]), "r"(a[1]), "r"(a[2]), "r"(a[3]), "r"(b[0]), "r"(b[1]));
}

// ---------------------------------------------------------------------------
// Prepass: x fp32 -> fp16 (25 MB, ~6.5 us)
// ---------------------------------------------------------------------------
__global__ void conv_x_kernel(const float* __restrict__ x) {
    size_t i = ((size_t)blockIdx.x * blockDim.x + threadIdx.x) * 8;
    float4 v0 = *(const float4*)(x + i);
    float4 v1 = *(const float4*)(x + i + 4);
    __half2 h[4];
    h[0] = __floats2half2_rn(v0.x, v0.y);
    h[1] = __floats2half2_rn(v0.z, v0.w);
    h[2] = __floats2half2_rn(v1.x, v1.y);
    h[3] = __floats2half2_rn(v1.z, v1.w);
    *(uint4*)(g_xh + i) = *(uint4*)h;
}

// ---------------------------------------------------------------------------
// Fused kernel: interleaved W-conversion blocks + gemm CTAs.
//   bid % 27 != 26 : convert one W row (2048 fp32 -> fp16), bump panel counter
//   bid % 27 == 26 : gemm CTA j = bid/27 (tile = j>>4, n0 = (j&15)*128);
//                    spins until its W panel is converted.
// Deadlock-free: conv blocks never wait and precede (in id order) all gemm
// CTAs needing them; dispatch is monotonic in block id.
// ---------------------------------------------------------------------------
__global__ __launch_bounds__(128, 2)
void moe_fused(const float* __restrict__ w,
               const int*   __restrict__ ssi,
               const int*   __restrict__ eoff) {
    const int bid = blockIdx.x;
    const int sub = bid % GRP;
    const int grp = bid / GRP;
    const int tid = threadIdx.x;

    if (sub != GRP - 1) {
        // ---------------- conversion role: one W row ----------------
        const int c = grp * (GRP - 1) + sub;
        if (c >= NCONV_ROWS) return;
        const float4* src = (const float4*)w + (size_t)c * 512;
        uint2* dst = (uint2*)g_wh + (size_t)c * 512;
        float4 v[4];
        #pragma unroll
        for (int q = 0; q < 4; q++) v[q] = src[tid + 128 * q];
        #pragma unroll
        for (int q = 0; q < 4; q++) {
            __half2 h0 = __floats2half2_rn(v[q].x, v[q].y);
            __half2 h1 = __floats2half2_rn(v[q].z, v[q].w);
            dst[tid + 128 * q] = make_uint2(*(uint32_t*)&h0, *(uint32_t*)&h1);
        }
        __threadfence();
        __syncthreads();
        if (tid == 0) atomicAdd(&g_cnt[c >> 7], 1);
        return;
    }

    // ---------------- gemm role ----------------
    const int j    = grp;              // 0..639
    const int tile = j >> 4;
    const int n0   = (j & 15) << 7;

    int e = -1, m0 = 0, rows = 0;
    {
        int nt = 0, prev = 0;
        #pragma unroll
        for (int ee = 0; ee < NE; ee++) {
            int end = __ldg(eoff + ee);
            int t = (end - prev + BM - 1) >> 7;
            if (e < 0 && tile < nt + t) {
                e = ee;
                m0 = prev + (tile - nt) * BM;
                int rem = end - m0;
                rows = rem < BM ? rem : BM;
            }
            nt += t;
            prev = end;
        }
    }
    if (e < 0) return;

    // Wait for this CTA's W panel (rows e*2048+n0 .. +127) to be converted.
    const int panel = e * 16 + (j & 15);
    if (tid == 0) {
        while (atomicAdd(&g_cnt[panel], 0) < 128) __nanosleep(256);
        __threadfence();
    }
    __syncthreads();

    extern __shared__ char smem[];
    const uint32_t sb = smem_u32(smem);
    const int wid  = tid >> 5;
    const int lane = tid & 31;
    const int warp_m = wid & 1;
    const int warp_n = wid >> 1;

    int* s_flat = (int*)(smem + SM_FLAT);
    if (tid < BM) s_flat[tid] = (tid < rows) ? ssi[m0 + tid] : -1;
    __syncthreads();

    // cp.async mapping: thread owns chunks {tid + 128q} (q=0..3) per tile
    const int c16 = (tid & 3) * 8;
    const __half* aptr[4];
    const __half* bptr[4];
    uint32_t dofs[4];
    #pragma unroll
    for (int q = 0; q < 4; q++) {
        const int r = (tid >> 2) + 32 * q;
        const int fl = s_flat[r];
        const int tk = (fl >= 0 ? fl : 0) >> 1;
        aptr[q] = g_xh + (size_t)tk * D_IN + c16;
        bptr[q] = g_wh + ((size_t)e * D_OUT + (size_t)(n0 + r)) * D_IN + c16;
        dofs[q] = SW((uint32_t)(r * 64 + (tid & 3) * 16));
    }

    // ldmatrix offsets (proven layout)
    uint32_t a_off[2][4], b_off[2][4];
    #pragma unroll
    for (int s = 0; s < 2; s++) {
        #pragma unroll
        for (int i = 0; i < 4; i++) {
            int arow = warp_m * 64 + i * 16 + (lane & 7) + ((lane >> 3) & 1) * 8;
            int ach  = s * 2 + (lane >> 4);
            a_off[s][i] = SW((uint32_t)(arow * 64 + ach * 16));
        }
        #pragma unroll
        for (int jp = 0; jp < 4; jp++) {
            int brow = warp_n * 64 + (jp * 2 + (lane >> 4)) * 8 + (lane & 7);
            int bch  = s * 2 + ((lane >> 3) & 1);
            b_off[s][jp] = SW((uint32_t)(brow * 64 + bch * 16));
        }
    }

    auto issue = [&](int kt) {
        const uint32_t stg = sb + SM_TILES + (uint32_t)(kt & 3) * STAGE_B;
        const int k = kt * KT;
        #pragma unroll
        for (int q = 0; q < 4; q++) {
            cp16(stg + T_AH + dofs[q], aptr[q] + k);
            cp16(stg + T_BH + dofs[q], bptr[q] + k);
        }
    };

    float acc[4][8][4];
    #pragma unroll
    for (int i = 0; i < 4; i++)
        #pragma unroll
        for (int jj = 0; jj < 8; jj++)
            #pragma unroll
            for (int q = 0; q < 4; q++) acc[i][jj][q] = 0.0f;

    issue(0); cp_commit();
    issue(1); cp_commit();
    issue(2); cp_commit();

    for (int it = 0; it < NT; it++) {
        cp_wait2();          // tile it resident
        __syncthreads();     // all warps done with iter it-1 -> slot reuse safe

        if (it + 3 < NT) issue(it + 3);
        cp_commit();

        const uint32_t stg = sb + SM_TILES + (uint32_t)(it & 3) * STAGE_B;
        #pragma unroll
        for (int s = 0; s < 2; s++) {
            uint32_t ah[4][4], bh[4][4];
            #pragma unroll
            for (int i = 0; i < 4; i++)
                ldm_x4(ah[i][0], ah[i][1], ah[i][2], ah[i][3], stg + T_AH + a_off[s][i]);
            #pragma unroll
            for (int jp = 0; jp < 4; jp++)
                ldm_x4(bh[jp][0], bh[jp][1], bh[jp][2], bh[jp][3], stg + T_BH + b_off[s][jp]);
            #pragma unroll
            for (int i = 0; i < 4; i++) {
                #pragma unroll
                for (int jp = 0; jp < 4; jp++) {
                    mma_fp16(acc[i][2 * jp],     ah[i], &bh[jp][0]);
                    mma_fp16(acc[i][2 * jp + 1], ah[i], &bh[jp][2]);
                }
            }
        }
        // no trailing sync: next iter's top sync closes all hazards
    }

    // Epilogue: scatter fp32 y (R6-proven)
    #pragma unroll
    for (int i = 0; i < 4; i++) {
        const int mr0 = warp_m * 64 + i * 16 + (lane >> 2);
        const int fl0 = s_flat[mr0];
        const int fl1 = s_flat[mr0 + 8];
        #pragma unroll
        for (int jj = 0; jj < 8; jj++) {
            const int col = n0 + warp_n * 64 + jj * 8 + (lane & 3) * 2;
            if (fl0 >= 0)
                *(float2*)(g_y + (size_t)fl0 * D_OUT + col) =
                    make_float2(acc[i][jj][0], acc[i][jj][1]);
            if (fl1 >= 0)
                *(float2*)(g_y + (size_t)fl1 * D_OUT + col) =
                    make_float2(acc[i][jj][2], acc[i][jj][3]);
        }
    }
}

// ---------------------------------------------------------------------------
__global__ void combine_kernel(const float* __restrict__ gates,
                               float* __restrict__ out) {
    int idx = blockIdx.x * blockDim.x + threadIdx.x;
    int n  = idx >> 9;
    int d4 = idx & 511;
    float g0 = gates[2 * n];
    float g1 = gates[2 * n + 1];
    const float4* y0 = (const float4*)(g_y + (size_t)(2 * n)     * D_OUT) + d4;
    const float4* y1 = (const float4*)(g_y + (size_t)(2 * n + 1) * D_OUT) + d4;
    float4 a = *y0, b = *y1, o;
    o.x = g0 * a.x + g1 * b.x;
    o.y = g0 * a.y + g1 * b.y;
    o.z = g0 * a.z + g1 * b.z;
    o.w = g0 * a.w + g1 * b.w;
    ((float4*)out)[idx] = o;
}

// ---------------------------------------------------------------------------
extern "C" void kernel_launch(void* const* d_in, const int* in_sizes, int n_in,
                              void* d_out, int out_size) {
    const float* x     = (const float*)d_in[0];
    const float* w     = (const float*)d_in[1];
    const int*   ssi   = (const int*)  d_in[4];
    const int*   eoff  = (const int*)  d_in[6];
    const float* gates = (const float*)d_in[7];
    float* out = (float*)d_out;

    // Reset panel counters (graph-capturable, no allocation)
    void* cnt_ptr = nullptr;
    cudaGetSymbolAddress(&cnt_ptr, g_cnt);
    cudaMemsetAsync(cnt_ptr, 0, NPANEL * sizeof(int));

    conv_x_kernel<<<(N_TOK * D_IN) / (256 * 8), 256>>>(x);

    cudaFuncSetAttribute(moe_fused,
                         cudaFuncAttributeMaxDynamicSharedMemorySize, SMEM_TOTAL);
    moe_fused<<<NGEMM * GRP, 128, SMEM_TOTAL>>>(w, ssi, eoff);

    combine_kernel<<<(N_TOK * (D_OUT / 4)) / 256, 256>>>(gates, out);
}